// round 14
// baseline (speedup 1.0000x reference)
#include <cuda_runtime.h>
#include <cuda_fp16.h>
#include <cstdint>

// VQ nearest-codebook lookup via 3-term FP16 mma.sync distance GEMM.
// R14: fp16 hi/lo split precomputed to GMEM (same bytes as f32 input),
// main loop = cp.async ring -> ldmatrix -> mma. No LDG staging, no cvt,
// no STS in the hot loop.
//   z_e_x: [16,2048,256] f32 -> N=32768 rows, D=256
//   embedding: [1024,256] f32 -> K=1024 codes
// d_out (f32): z_q_x [N*D] @0, z_q_x_bar [N*D] @8388608, indices [N] @16777216
// argmax_k(x.c - ||c||^2/2); keep hh + hl + lh terms.

#define NTOK   32768
#define DDIM   256
#define KCODE  1024
#define BM     128
#define BN     128
#define KS     32              // k per stage (two k16 chunks)
#define NTILE  8
#define NG     64              // NTILE * (DDIM/KS)
#define PITCHH 40              // halves per row (80B pitch, ldsm conflict-free)

#define OUT_BAR   8388608
#define OUT_IDX  16777216

#define MAT_B  (BM * PITCHH * 2)     // 10240 bytes per matrix-stage
#define SLOT_B (4 * MAT_B)           // Ah, Al, Bh, Bl = 40960 bytes
#define CN_F   (2 * SLOT_B / 4)      // float index after 2 ring slots = 20480
#define DYN_SMEM (2 * SLOT_B + KCODE * 4)   // 86016 B

__device__ float g_cnorm[KCODE];
__device__ __align__(16) __half g_xh[NTOK * DDIM];
__device__ __align__(16) __half g_xl[NTOK * DDIM];
__device__ __align__(16) __half g_ch[KCODE * DDIM];
__device__ __align__(16) __half g_cl[KCODE * DDIM];

// ---------------------------------------------------------------------------
__device__ __forceinline__ uint32_t smem_u32(const void* p) {
    uint32_t a;
    asm("{ .reg .u64 t; cvta.to.shared.u64 t, %1; cvt.u32.u64 %0, t; }"
        : "=r"(a) : "l"(p));
    return a;
}
#define LDSM4(r, addr) \
    asm volatile("ldmatrix.sync.aligned.m8n8.x4.shared.b16 {%0,%1,%2,%3}, [%4];" \
        : "=r"((r)[0]), "=r"((r)[1]), "=r"((r)[2]), "=r"((r)[3]) : "r"(addr))

#define CP_ASYNC16(dst, src) \
    asm volatile("cp.async.cg.shared.global [%0], [%1], 16;" :: "r"(dst), "l"(src))
#define CP_COMMIT() asm volatile("cp.async.commit_group;" ::: "memory")
#define CP_WAIT1()  asm volatile("cp.async.wait_group 1;" ::: "memory")

__device__ __forceinline__ void mma_f16(float* c, const uint32_t* a,
                                        uint32_t b0, uint32_t b1) {
    asm volatile(
        "mma.sync.aligned.m16n8k16.row.col.f32.f16.f16.f32 "
        "{%0,%1,%2,%3}, {%4,%5,%6,%7}, {%8,%9}, {%0,%1,%2,%3};"
        : "+f"(c[0]), "+f"(c[1]), "+f"(c[2]), "+f"(c[3])
        : "r"(a[0]), "r"(a[1]), "r"(a[2]), "r"(a[3]), "r"(b0), "r"(b1));
}

__device__ __forceinline__ uint32_t h2u(__half2 v) {
    return *reinterpret_cast<uint32_t*>(&v);
}

__device__ __forceinline__ void split_f4(float4 v, uint2& h, uint2& l) {
    __half2 h01 = __floats2half2_rn(v.x, v.y);
    __half2 h23 = __floats2half2_rn(v.z, v.w);
    float2 f01 = __half22float2(h01);
    float2 f23 = __half22float2(h23);
    __half2 l01 = __floats2half2_rn(v.x - f01.x, v.y - f01.y);
    __half2 l23 = __floats2half2_rn(v.z - f23.x, v.w - f23.y);
    h.x = h2u(h01); h.y = h2u(h23);
    l.x = h2u(l01); l.y = h2u(l23);
}

// ---------------------------------------------------------------------------
__global__ void cnorm_kernel(const float* __restrict__ emb) {
    int warp = (blockIdx.x * blockDim.x + threadIdx.x) >> 5;
    int lane = threadIdx.x & 31;
    if (warp >= KCODE) return;
    const float* row = emb + (size_t)warp * DDIM;
    float s = 0.f;
    #pragma unroll
    for (int k = lane; k < DDIM; k += 32) { float v = row[k]; s += v * v; }
    #pragma unroll
    for (int o = 16; o; o >>= 1) s += __shfl_xor_sync(0xffffffffu, s, o);
    if (lane == 0) g_cnorm[warp] = s;
}

__global__ void split_x_kernel(const float* __restrict__ x) {
    size_t i = ((size_t)blockIdx.x * 256 + threadIdx.x) * 4;
    float4 v = *(const float4*)(x + i);
    uint2 h, l;
    split_f4(v, h, l);
    *(uint2*)(g_xh + i) = h;
    *(uint2*)(g_xl + i) = l;
}

__global__ void split_c_kernel(const float* __restrict__ emb) {
    size_t i = ((size_t)blockIdx.x * 256 + threadIdx.x) * 4;
    float4 v = *(const float4*)(emb + i);
    uint2 h, l;
    split_f4(v, h, l);
    *(uint2*)(g_ch + i) = h;
    *(uint2*)(g_cl + i) = l;
}

// ---------------------------------------------------------------------------
// 256 threads = 8 warps in 4(m) x 2(n); warp tile 32 rows x 64 codes.
// ---------------------------------------------------------------------------
__global__ __launch_bounds__(256, 2)
void vq_mma_kernel(const float* __restrict__ emb, float* __restrict__ out) {
    extern __shared__ float dsm[];
    __shared__ float sV[2][BM];
    __shared__ int   sI[2][BM];
    __shared__ int   bidx_s[BM];

    const int tid = threadIdx.x;
    const int wid = tid >> 5;
    const int L   = tid & 31;
    const int rowBase = blockIdx.x * BM;
    const int mbase = (wid >> 1) * 32;       // 0/32/64/96
    const int nbase = (wid & 1) * 64;        // 0/64

    const uint32_t SB = smem_u32(dsm);

    // ldmatrix lane geometry (byte offsets inside a matrix-stage; 80B pitch)
    const int aRow = (L & 7) + 8 * ((L >> 3) & 1);
    const int aK   = (L >> 4) * 16;
    const uint32_t aBase = (uint32_t)((mbase + aRow) * 80 + aK);
    const uint32_t bBase = (uint32_t)((nbase + aRow) * 80 + aK);

    // cnorm table into smem (once)
    #pragma unroll
    for (int i = 0; i < 4; ++i) dsm[CN_F + tid + 256 * i] = g_cnorm[tid + 256 * i];

    float bV[4];
    int   bI[4];
    #pragma unroll
    for (int i = 0; i < 4; ++i) { bV[i] = -3.4e38f; bI[i] = 0x7fffffff; }

    // cp.async: per matrix, 512 16B-chunks; thread covers 2 (tid, tid+256)
    #define ISSUE(sidx) do { \
        if ((sidx) < NG) { \
            const int _t  = (sidx) >> 3; \
            const int _ks = ((sidx) & 7) * KS; \
            const uint32_t _base = SB + (uint32_t)(((sidx) & 1) * SLOT_B); \
            _Pragma("unroll") \
            for (int _j = 0; _j < 2; ++_j) { \
                const int _w = tid + 256 * _j; \
                const int _row = _w >> 2; \
                const int _sl  = _w & 3; \
                const uint32_t _o = (uint32_t)(_row * 80 + _sl * 16); \
                const size_t _gx = (size_t)(rowBase + _row) * DDIM + _ks + _sl * 8; \
                const size_t _gc = (size_t)(_t * BN + _row) * DDIM + _ks + _sl * 8; \
                CP_ASYNC16(_base + _o,             g_xh + _gx); \
                CP_ASYNC16(_base + MAT_B + _o,     g_xl + _gx); \
                CP_ASYNC16(_base + 2 * MAT_B + _o, g_ch + _gc); \
                CP_ASYNC16(_base + 3 * MAT_B + _o, g_cl + _gc); \
            } \
        } \
        CP_COMMIT(); \
    } while (0)

    float acc[2][8][4];
    #pragma unroll
    for (int f = 0; f < 2; ++f)
        #pragma unroll
        for (int n = 0; n < 8; ++n)
            #pragma unroll
            for (int e = 0; e < 4; ++e) acc[f][n][e] = 0.f;

    ISSUE(0);
    ISSUE(1);

    for (int g = 0; g < NG; ++g) {
        CP_WAIT1();             // stage g resident
        __syncthreads();

        const uint32_t SL  = SB + (uint32_t)((g & 1) * SLOT_B);
        const uint32_t AHB = SL;
        const uint32_t ALB = SL + MAT_B;
        const uint32_t BHB = SL + 2 * MAT_B;
        const uint32_t BLB = SL + 3 * MAT_B;

        #pragma unroll
        for (int kk = 0; kk < 2; ++kk) {
            const uint32_t kof = (uint32_t)(kk * 32);
            uint32_t ah[2][4], al[2][4], bh[4][4], bl[4][4];
            #pragma unroll
            for (int f = 0; f < 2; ++f) LDSM4(ah[f], AHB + aBase + f * 1280 + kof);
            #pragma unroll
            for (int q = 0; q < 4; ++q) LDSM4(bh[q], BHB + bBase + q * 1280 + kof);
            #pragma unroll
            for (int f = 0; f < 2; ++f)
                #pragma unroll
                for (int q = 0; q < 4; ++q) {
                    mma_f16(acc[f][2 * q],     ah[f], bh[q][0], bh[q][2]);
                    mma_f16(acc[f][2 * q + 1], ah[f], bh[q][1], bh[q][3]);
                }
            #pragma unroll
            for (int q = 0; q < 4; ++q) LDSM4(bl[q], BLB + bBase + q * 1280 + kof);
            #pragma unroll
            for (int f = 0; f < 2; ++f)
                #pragma unroll
                for (int q = 0; q < 4; ++q) {
                    mma_f16(acc[f][2 * q],     ah[f], bl[q][0], bl[q][2]);
                    mma_f16(acc[f][2 * q + 1], ah[f], bl[q][1], bl[q][3]);
                }
            #pragma unroll
            for (int f = 0; f < 2; ++f) LDSM4(al[f], ALB + aBase + f * 1280 + kof);
            #pragma unroll
            for (int f = 0; f < 2; ++f)
                #pragma unroll
                for (int q = 0; q < 4; ++q) {
                    mma_f16(acc[f][2 * q],     al[f], bh[q][0], bh[q][2]);
                    mma_f16(acc[f][2 * q + 1], al[f], bh[q][1], bh[q][3]);
                }
        }

        // ---- tile epilogue: fold norms, update per-lane argmax ----
        if ((g & 7) == 7) {
            const int cb = (g >> 3) * BN;
            #pragma unroll
            for (int n = 0; n < 8; ++n) {
                #pragma unroll
                for (int e = 0; e < 2; ++e) {
                    const int ci = cb + nbase + 8 * n + 2 * (L & 3) + e;
                    const float hc = -0.5f * dsm[CN_F + ci];
                    #pragma unroll
                    for (int f = 0; f < 2; ++f) {
                        float vlo = acc[f][n][e]     + hc;
                        float vhi = acc[f][n][2 + e] + hc;
                        if (vlo > bV[2 * f])     { bV[2 * f] = vlo;     bI[2 * f] = ci; }
                        if (vhi > bV[2 * f + 1]) { bV[2 * f + 1] = vhi; bI[2 * f + 1] = ci; }
                    }
                }
            }
            if (g + 1 < NG) {
                #pragma unroll
                for (int f = 0; f < 2; ++f)
                    #pragma unroll
                    for (int n = 0; n < 8; ++n)
                        #pragma unroll
                        for (int e = 0; e < 4; ++e) acc[f][n][e] = 0.f;
            }
        }
        __syncthreads();        // all warps done reading slot g&1
        ISSUE(g + 2);           // refill it
    }

    // quad reduce (lanes sharing L>>2 cover the same rows)
    #pragma unroll
    for (int i = 0; i < 4; ++i) {
        float v = bV[i]; int idx = bI[i];
        #pragma unroll
        for (int o = 1; o < 4; o <<= 1) {
            float vo = __shfl_xor_sync(0xffffffffu, v, o);
            int   io = __shfl_xor_sync(0xffffffffu, idx, o);
            if (vo > v || (vo == v && io < idx)) { v = vo; idx = io; }
        }
        bV[i] = v; bI[i] = idx;
    }
    if ((L & 3) == 0) {
        const int wn = wid & 1;
        #pragma unroll
        for (int f = 0; f < 2; ++f)
            #pragma unroll
            for (int h = 0; h < 2; ++h) {
                int row = mbase + 16 * f + 8 * h + (L >> 2);
                sV[wn][row] = bV[2 * f + h];
                sI[wn][row] = bI[2 * f + h];
            }
    }
    __syncthreads();

    // combine the two n-warps, publish winners
    if (tid < BM) {
        float v0 = sV[0][tid], v1 = sV[1][tid];
        int   i0 = sI[0][tid], i1 = sI[1][tid];
        int idx = (v1 > v0 || (v1 == v0 && i1 < i0)) ? i1 : i0;
        bidx_s[tid] = idx;
        out[OUT_IDX + rowBase + tid] = (float)idx;
    }
    __syncthreads();

    // gather codes, write z_q_x and z_q_x_bar
    const float4* emb4 = (const float4*)emb;
    float4* o4 = (float4*)out;
    #pragma unroll 4
    for (int it = 0; it < 32; ++it) {
        int gg = tid + it * 256;         // 0..8191
        int m = gg >> 6;                 // 0..127
        int q = gg & 63;
        int code = bidx_s[m];
        float4 v = emb4[(size_t)code * 64 + q];
        size_t off = (size_t)(rowBase + m) * 64 + q;
        o4[off] = v;
        o4[off + (OUT_BAR / 4)] = v;
    }
}

// ---------------------------------------------------------------------------
extern "C" void kernel_launch(void* const* d_in, const int* in_sizes, int n_in,
                              void* d_out, int out_size) {
    const float* x   = (const float*)d_in[0];
    const float* emb = (const float*)d_in[1];
    float* out = (float*)d_out;

    cudaFuncSetAttribute(vq_mma_kernel, cudaFuncAttributeMaxDynamicSharedMemorySize, DYN_SMEM);

    cnorm_kernel<<<KCODE / 8, 256>>>(emb);
    split_x_kernel<<<NTOK * DDIM / 4 / 256, 256>>>(x);
    split_c_kernel<<<KCODE * DDIM / 4 / 256, 256>>>(emb);
    vq_mma_kernel<<<NTOK / BM, 256, DYN_SMEM>>>(emb, out);
}

// round 15
// speedup vs baseline: 1.1114x; 1.1114x over previous
#include <cuda_runtime.h>
#include <cuda_fp16.h>
#include <cstdint>

// VQ nearest-codebook lookup via 3-term FP16 mma.sync distance GEMM.
// R15: R10's proven in-kernel-split pipeline, but 4-way code-split for load
// balance (grid 1024 quarter-CTAs over 148 SMs -> ~1% imbalance vs 15.6%).
// Per-CTA candidates merged + gathered by a small second kernel.
//   z_e_x: [16,2048,256] f32 -> N=32768 rows, D=256
//   embedding: [1024,256] f32 -> K=1024 codes
// d_out (f32): z_q_x [N*D] @0, z_q_x_bar [N*D] @8388608, indices [N] @16777216
// argmax_k(x.c - ||c||^2/2); x = xh + xl (fp16 split), keep hh + hl + lh.

#define NTOK   32768
#define DDIM   256
#define KCODE  1024
#define BM     128
#define BN     128
#define NSEG   4
#define SEGK   256             // codes per CTA (2 tiles of BN)
#define KS     32              // k per stage (two k16 chunks)
#define NG     16              // 2 tiles * 8 stages
#define PITCHH 40              // halves per row (80B pitch, ldsm conflict-free)

#define OUT_BAR   8388608
#define OUT_IDX  16777216

// half-indexed layout inside dynamic smem
#define MAT_H   (BM * PITCHH)        // 5120 halves per matrix-stage
#define SLOT_H  (4 * MAT_H)          // Ah, Al, Bh, Bl
#define CN_F    (SLOT_H)             // float index after 2 slots (2*20480 halves)
#define DYN_SMEM (CN_F * 4 + SEGK * 4)   // 81920 + 1024 = 82944 B

__device__ float g_cnorm[KCODE];
__device__ float g_candV[NSEG * NTOK];
__device__ int   g_candI[NSEG * NTOK];

// ---------------------------------------------------------------------------
__device__ __forceinline__ uint32_t smem_u32(const void* p) {
    uint32_t a;
    asm("{ .reg .u64 t; cvta.to.shared.u64 t, %1; cvt.u32.u64 %0, t; }"
        : "=r"(a) : "l"(p));
    return a;
}
#define LDSM4(r, addr) \
    asm volatile("ldmatrix.sync.aligned.m8n8.x4.shared.b16 {%0,%1,%2,%3}, [%4];" \
        : "=r"((r)[0]), "=r"((r)[1]), "=r"((r)[2]), "=r"((r)[3]) : "r"(addr))

__device__ __forceinline__ void mma_f16(float* c, const uint32_t* a,
                                        uint32_t b0, uint32_t b1) {
    asm volatile(
        "mma.sync.aligned.m16n8k16.row.col.f32.f16.f16.f32 "
        "{%0,%1,%2,%3}, {%4,%5,%6,%7}, {%8,%9}, {%0,%1,%2,%3};"
        : "+f"(c[0]), "+f"(c[1]), "+f"(c[2]), "+f"(c[3])
        : "r"(a[0]), "r"(a[1]), "r"(a[2]), "r"(a[3]), "r"(b0), "r"(b1));
}

__device__ __forceinline__ uint32_t h2u(__half2 v) {
    return *reinterpret_cast<uint32_t*>(&v);
}

// split one float4 into fp16 hi (uint2) and fp16 lo (uint2)
__device__ __forceinline__ void split_f4(float4 v, uint2& h, uint2& l) {
    __half2 h01 = __floats2half2_rn(v.x, v.y);
    __half2 h23 = __floats2half2_rn(v.z, v.w);
    float2 f01 = __half22float2(h01);
    float2 f23 = __half22float2(h23);
    __half2 l01 = __floats2half2_rn(v.x - f01.x, v.y - f01.y);
    __half2 l23 = __floats2half2_rn(v.z - f23.x, v.w - f23.y);
    h.x = h2u(h01); h.y = h2u(h23);
    l.x = h2u(l01); l.y = h2u(l23);
}

// ---------------------------------------------------------------------------
__global__ void cnorm_kernel(const float* __restrict__ emb) {
    int warp = (blockIdx.x * blockDim.x + threadIdx.x) >> 5;
    int lane = threadIdx.x & 31;
    if (warp >= KCODE) return;
    const float* row = emb + (size_t)warp * DDIM;
    float s = 0.f;
    #pragma unroll
    for (int k = lane; k < DDIM; k += 32) { float v = row[k]; s += v * v; }
    #pragma unroll
    for (int o = 16; o; o >>= 1) s += __shfl_xor_sync(0xffffffffu, s, o);
    if (lane == 0) g_cnorm[warp] = s;
}

// ---------------------------------------------------------------------------
// 256 threads = 8 warps in 4(m) x 2(n); warp tile 32 rows x 64 codes.
// CTA b: rows [(b>>2)*128, +128), codes [(b&3)*256, +256).
// ---------------------------------------------------------------------------
__global__ __launch_bounds__(256, 2)
void vq_mma_kernel(const float* __restrict__ x,
                   const float* __restrict__ emb,
                   float* __restrict__ out) {
    extern __shared__ float dsm[];
    __half* hsm = (__half*)dsm;
    __shared__ float sV[2][BM];
    __shared__ int   sI[2][BM];

    const int tid = threadIdx.x;
    const int wid = tid >> 5;
    const int L   = tid & 31;
    const int rowBase  = (blockIdx.x >> 2) * BM;
    const int segBase  = (blockIdx.x & 3) * SEGK;
    const int mbase = (wid >> 1) * 32;       // 0/32/64/96
    const int nbase = (wid & 1) * 64;        // 0/64

    const uint32_t SB = smem_u32(dsm);

    // ldmatrix lane geometry (byte offsets inside a matrix-stage; 80B pitch)
    const int aRow = (L & 7) + 8 * ((L >> 3) & 1);
    const int aK   = (L >> 4) * 16;
    const uint32_t aBase = (uint32_t)((mbase + aRow) * 80 + aK);
    const uint32_t bBase = (uint32_t)((nbase + aRow) * 80 + aK);

    // loader geometry: row = tid>>1, 16-half chunk = (tid&1)*16
    const int lRow = tid >> 1;
    const int lKh  = (tid & 1) * 16;

    // this segment's cnorms into smem
    dsm[CN_F + tid] = g_cnorm[segBase + tid];

    float bV[4];
    int   bI[4];
    #pragma unroll
    for (int i = 0; i < 4; ++i) { bV[i] = -3.4e38f; bI[i] = 0x7fffffff; }

    float4 vS[4];

    #define LOAD_A(sidx) do { \
        const int _ko = ((sidx) & 7) * KS + lKh; \
        const float* xp = x + (size_t)(rowBase + lRow) * DDIM + _ko; \
        vS[0] = *(const float4*)(xp); \
        vS[1] = *(const float4*)(xp + 4); \
        vS[2] = *(const float4*)(xp + 8); \
        vS[3] = *(const float4*)(xp + 12); \
    } while (0)

    #define LOAD_B(sidx) do { \
        const int _t  = (sidx) >> 3; \
        const int _ko = ((sidx) & 7) * KS + lKh; \
        const float* bp = emb + (size_t)(segBase + _t * BN + lRow) * DDIM + _ko; \
        vS[0] = *(const float4*)(bp); \
        vS[1] = *(const float4*)(bp + 4); \
        vS[2] = *(const float4*)(bp + 8); \
        vS[3] = *(const float4*)(bp + 12); \
    } while (0)

    // store 16 floats as hi/lo halves at matrix base (half index)
    #define STORE_SPLIT(hmatH, lmatH) do { \
        const int _hb = lRow * PITCHH + lKh; \
        _Pragma("unroll") \
        for (int _i = 0; _i < 4; ++_i) { \
            uint2 _h, _l; \
            split_f4(vS[_i], _h, _l); \
            *(uint2*)&hsm[(hmatH) + _hb + 4 * _i] = _h; \
            *(uint2*)&hsm[(lmatH) + _hb + 4 * _i] = _l; \
        } \
    } while (0)

    float acc[2][8][4];
    #pragma unroll
    for (int f = 0; f < 2; ++f)
        #pragma unroll
        for (int n = 0; n < 8; ++n)
            #pragma unroll
            for (int e = 0; e < 4; ++e) acc[f][n][e] = 0.f;

    // prologue: stage 0 into buffer 0
    LOAD_A(0); STORE_SPLIT(0, MAT_H);
    LOAD_B(0); STORE_SPLIT(2 * MAT_H, 3 * MAT_H);
    __syncthreads();

    for (int g = 0; g < NG; ++g) {
        const int buf = g & 1;
        const uint32_t SL  = SB + (uint32_t)buf * (SLOT_H * 2);
        const uint32_t AHB = SL;
        const uint32_t ALB = SL + MAT_H * 2;
        const uint32_t BHB = SL + 2 * MAT_H * 2;
        const uint32_t BLB = SL + 3 * MAT_H * 2;
        const uint32_t nslot = (uint32_t)(buf ^ 1) * SLOT_H;

        if (g + 1 < NG) LOAD_A(g + 1);

        #pragma unroll
        for (int kk = 0; kk < 2; ++kk) {
            const uint32_t kof = (uint32_t)(kk * 32);
            uint32_t ah[2][4], al[2][4], bh[4][4], bl[4][4];
            #pragma unroll
            for (int f = 0; f < 2; ++f) LDSM4(ah[f], AHB + aBase + f * 1280 + kof);
            #pragma unroll
            for (int q = 0; q < 4; ++q) LDSM4(bh[q], BHB + bBase + q * 1280 + kof);
            #pragma unroll
            for (int f = 0; f < 2; ++f)
                #pragma unroll
                for (int q = 0; q < 4; ++q) {
                    mma_f16(acc[f][2 * q],     ah[f], bh[q][0], bh[q][2]);
                    mma_f16(acc[f][2 * q + 1], ah[f], bh[q][1], bh[q][3]);
                }
            #pragma unroll
            for (int q = 0; q < 4; ++q) LDSM4(bl[q], BLB + bBase + q * 1280 + kof);
            #pragma unroll
            for (int f = 0; f < 2; ++f)
                #pragma unroll
                for (int q = 0; q < 4; ++q) {
                    mma_f16(acc[f][2 * q],     ah[f], bl[q][0], bl[q][2]);
                    mma_f16(acc[f][2 * q + 1], ah[f], bl[q][1], bl[q][3]);
                }
            #pragma unroll
            for (int f = 0; f < 2; ++f) LDSM4(al[f], ALB + aBase + f * 1280 + kof);
            #pragma unroll
            for (int f = 0; f < 2; ++f)
                #pragma unroll
                for (int q = 0; q < 4; ++q) {
                    mma_f16(acc[f][2 * q],     al[f], bh[q][0], bh[q][2]);
                    mma_f16(acc[f][2 * q + 1], al[f], bh[q][1], bh[q][3]);
                }

            if (kk == 0) {
                if (g + 1 < NG) {
                    STORE_SPLIT(nslot, nslot + MAT_H);        // A halves -> other buffer
                    LOAD_B(g + 1);
                }
            } else {
                if (g + 1 < NG)
                    STORE_SPLIT(nslot + 2 * MAT_H, nslot + 3 * MAT_H);  // B halves
            }
        }

        // ---- tile epilogue: fold norms, update per-lane argmax ----
        if ((g & 7) == 7) {
            const int cbl = (g >> 3) * BN;       // local code base (0 or 128)
            #pragma unroll
            for (int n = 0; n < 8; ++n) {
                #pragma unroll
                for (int e = 0; e < 2; ++e) {
                    const int cil = cbl + nbase + 8 * n + 2 * (L & 3) + e;
                    const int ci  = segBase + cil;
                    const float hc = -0.5f * dsm[CN_F + cil];
                    #pragma unroll
                    for (int f = 0; f < 2; ++f) {
                        float vlo = acc[f][n][e]     + hc;
                        float vhi = acc[f][n][2 + e] + hc;
                        if (vlo > bV[2 * f])     { bV[2 * f] = vlo;     bI[2 * f] = ci; }
                        if (vhi > bV[2 * f + 1]) { bV[2 * f + 1] = vhi; bI[2 * f + 1] = ci; }
                    }
                }
            }
            if (g + 1 < NG) {
                #pragma unroll
                for (int f = 0; f < 2; ++f)
                    #pragma unroll
                    for (int n = 0; n < 8; ++n)
                        #pragma unroll
                        for (int e = 0; e < 4; ++e) acc[f][n][e] = 0.f;
            }
        }
        __syncthreads();
    }

    // quad reduce (lanes sharing L>>2 cover the same rows)
    #pragma unroll
    for (int i = 0; i < 4; ++i) {
        float v = bV[i]; int idx = bI[i];
        #pragma unroll
        for (int o = 1; o < 4; o <<= 1) {
            float vo = __shfl_xor_sync(0xffffffffu, v, o);
            int   io = __shfl_xor_sync(0xffffffffu, idx, o);
            if (vo > v || (vo == v && io < idx)) { v = vo; idx = io; }
        }
        bV[i] = v; bI[i] = idx;
    }
    if ((L & 3) == 0) {
        const int wn = wid & 1;
        #pragma unroll
        for (int f = 0; f < 2; ++f)
            #pragma unroll
            for (int h = 0; h < 2; ++h) {
                int row = mbase + 16 * f + 8 * h + (L >> 2);
                sV[wn][row] = bV[2 * f + h];
                sI[wn][row] = bI[2 * f + h];
            }
    }
    __syncthreads();

    // combine the two n-warps; publish this segment's per-row candidate
    if (tid < BM) {
        float v0 = sV[0][tid], v1 = sV[1][tid];
        int   i0 = sI[0][tid], i1 = sI[1][tid];
        float v  = v0; int idx = i0;
        if (v1 > v0 || (v1 == v0 && i1 < i0)) { v = v1; idx = i1; }
        const size_t slot = (size_t)(blockIdx.x & 3) * NTOK + rowBase + tid;
        g_candV[slot] = v;
        g_candI[slot] = idx;
    }
}

// ---------------------------------------------------------------------------
// Merge 4 segment candidates per row, write indices and gather outputs.
// 128 blocks x 256 threads; block covers 256 rows.
// ---------------------------------------------------------------------------
__global__ __launch_bounds__(256)
void merge_kernel(const float* __restrict__ emb, float* __restrict__ out) {
    __shared__ int bidx_s[256];
    const int tid = threadIdx.x;
    const int row = blockIdx.x * 256 + tid;

    float v = g_candV[row];
    int idx  = g_candI[row];
    #pragma unroll
    for (int s = 1; s < NSEG; ++s) {
        float vs = g_candV[(size_t)s * NTOK + row];
        int   is = g_candI[(size_t)s * NTOK + row];
        if (vs > v || (vs == v && is < idx)) { v = vs; idx = is; }
    }
    bidx_s[tid] = idx;
    out[OUT_IDX + row] = (float)idx;
    __syncthreads();

    const float4* emb4 = (const float4*)emb;
    float4* o4 = (float4*)out;
    const int rowBase = blockIdx.x * 256;
    #pragma unroll 4
    for (int it = 0; it < 64; ++it) {
        int gg = tid + it * 256;         // 0..16383
        int m = gg >> 6;                 // 0..255
        int q = gg & 63;
        int code = bidx_s[m];
        float4 val = emb4[(size_t)code * 64 + q];
        size_t off = (size_t)(rowBase + m) * 64 + q;
        o4[off] = val;
        o4[off + (OUT_BAR / 4)] = val;
    }
}

// ---------------------------------------------------------------------------
extern "C" void kernel_launch(void* const* d_in, const int* in_sizes, int n_in,
                              void* d_out, int out_size) {
    const float* x   = (const float*)d_in[0];
    const float* emb = (const float*)d_in[1];
    float* out = (float*)d_out;

    cudaFuncSetAttribute(vq_mma_kernel, cudaFuncAttributeMaxDynamicSharedMemorySize, DYN_SMEM);

    cnorm_kernel<<<KCODE / 8, 256>>>(emb);
    vq_mma_kernel<<<(NTOK / BM) * NSEG, 256, DYN_SMEM>>>(x, emb, out);
    merge_kernel<<<NTOK / 256, 256>>>(emb, out);
}